// round 16
// baseline (speedup 1.0000x reference)
#include <cuda_runtime.h>
#include <cuda_fp16.h>
#include <cstdint>
#include <math.h>

#define B_  2
#define T_  2048
#define C_  1024
#define H_  16
#define HD_ 64
#define NBH_ (B_*H_)     // 32
#define M_   (B_*T_)     // 4096

// Scratch (allocation-free: __device__ globals)
__device__ __half g_Qh[(size_t)NBH_ * T_ * HD_];   // pre-scaled by 0.125*log2(e)
__device__ __half g_Kh[(size_t)NBH_ * T_ * HD_];   // [bh][t][d]
__device__ __half g_Vth[(size_t)NBH_ * HD_ * T_];  // [bh][d][t]
__device__ __half g_xh[(size_t)M_ * C_];
__device__ __half g_yh[(size_t)M_ * C_];
__device__ __half g_wah[(size_t)3*C_ * C_];   // W_attn^T [n][k]
__device__ __half g_wph[(size_t)C_ * C_];     // W_proj^T [n][k]

// split-KV partials (unnormalized O + per-row (m,l))
__device__ float  g_Op0[(size_t)NBH_ * T_ * HD_];
__device__ float  g_Op1[(size_t)NBH_ * T_ * HD_];
__device__ float2 g_ml0[(size_t)NBH_ * T_];
__device__ float2 g_ml1[(size_t)NBH_ * T_];

#define QSCALE (0.125f * 1.4426950408889634f)   // (1/sqrt(64)) * log2(e)

// ---------------------------------------------------------------------------
// helpers
// ---------------------------------------------------------------------------
__device__ __forceinline__ uint32_t pack2h(float x, float y) {
    __half2 h = __floats2half2_rn(x, y);
    return *reinterpret_cast<uint32_t*>(&h);
}
__device__ __forceinline__ float ex2f(float x) {
    float r;
    asm("ex2.approx.f32 %0, %1;" : "=f"(r) : "f"(x));
    return r;
}

#define LDSM4(r0, r1, r2, r3, addr) \
    asm volatile("ldmatrix.sync.aligned.m8n8.x4.shared.b16 {%0,%1,%2,%3}, [%4];" \
        : "=r"(r0), "=r"(r1), "=r"(r2), "=r"(r3) : "r"(addr))

#define MMA_F16(d, a, b) \
    asm volatile("mma.sync.aligned.m16n8k16.row.col.f32.f16.f16.f32 " \
        "{%0,%1,%2,%3},{%4,%5,%6,%7},{%8,%9},{%0,%1,%2,%3};" \
        : "+f"((d)[0]), "+f"((d)[1]), "+f"((d)[2]), "+f"((d)[3]) \
        : "r"((a)[0]), "r"((a)[1]), "r"((a)[2]), "r"((a)[3]), \
          "r"((b)[0]), "r"((b)[1]))

__device__ __forceinline__ void cp16(uint32_t dst, const void* src) {
    asm volatile("cp.async.cg.shared.global [%0], [%1], 16;" :: "r"(dst), "l"(src));
}
#define CP_COMMIT() asm volatile("cp.async.commit_group;")

// ---------------------------------------------------------------------------
// Converters
// ---------------------------------------------------------------------------
__global__ void __launch_bounds__(256) round_f4(const float* __restrict__ src,
                                                __half* __restrict__ dst) {
    const int i = blockIdx.x * 256 + threadIdx.x;
    const float4 v = ((const float4*)src)[i];
    uint2 u = make_uint2(pack2h(v.x, v.y), pack2h(v.z, v.w));
    ((uint2*)dst)[i] = u;
}

template<int NC>
__global__ void __launch_bounds__(256) round_wt(const float* __restrict__ W,
                                                __half* __restrict__ th) {
    __shared__ float tile[32][33];
    const int n0 = blockIdx.x * 32, k0 = blockIdx.y * 32;
    const int tx = threadIdx.x & 31, ty = threadIdx.x >> 5;
    #pragma unroll
    for (int r = ty; r < 32; r += 8)
        tile[r][tx] = W[(size_t)(k0 + r) * NC + n0 + tx];
    __syncthreads();
    #pragma unroll
    for (int r = ty; r < 32; r += 8)
        th[(size_t)(n0 + r) * 1024 + k0 + tx] = __float2half_rn(tile[tx][r]);
}

// ---------------------------------------------------------------------------
// Epilogue scatter (round-14 verified form: bias added inside)
// ---------------------------------------------------------------------------
template<int MODE>
__device__ __forceinline__ void emit(int m, int n, float val,
                                     const float* __restrict__ bias,
                                     float* __restrict__ out) {
    val += bias[n];
    if (MODE == 0) {
        const int bb = m >> 11;
        const int t  = m & 2047;
        if (n < C_) {
            const int h = n >> 6, d = n & 63;
            g_Qh[(((size_t)(bb*H_ + h))*T_ + t)*HD_ + d] = __float2half_rn(val * QSCALE);
        } else if (n < 2*C_) {
            const int nn = n - C_;
            const int h = nn >> 6, d = nn & 63;
            g_Kh[(((size_t)(bb*H_ + h))*T_ + t)*HD_ + d] = __float2half_rn(val);
        } else {
            const int nn = n - 2*C_;
            const int h = nn >> 6, d = nn & 63;
            g_Vth[(((size_t)(bb*H_ + h))*HD_ + d)*T_ + t] = __float2half_rn(val);  // transposed
        }
    } else {
        out[(size_t)m * C_ + n] = val;
    }
}

// ---------------------------------------------------------------------------
// fp16 GEMM (round-13/14 verified config, byte-identical mainloop+epilogue)
// ---------------------------------------------------------------------------
#define ROWP 40
#define PLANEA (128*ROWP)
#define PLANEB (64*ROWP)
#define STG16  (PLANEA+PLANEB)
static const int GEMM_SMEM = 3 * STG16 * (int)sizeof(uint16_t);  // 46080 B

template<int MODE>
__global__ void __launch_bounds__(256, 4) gemm_f16(const __half* __restrict__ A,
                                                   const __half* __restrict__ Bh,
                                                   const float* __restrict__ bias,
                                                   float* __restrict__ out) {
    extern __shared__ __align__(16) uint16_t sm16[];
    const int tid  = threadIdx.x;
    const int lane = tid & 31, wid = tid >> 5;
    const int wm = wid >> 1, wn = wid & 1;          // 4m x 2n warps
    const int m0 = blockIdx.y * 128, n0 = blockIdx.x * 64;

    const uint32_t sm_base = (uint32_t)__cvta_generic_to_shared(sm16);

    const int arow = tid >> 1;
    const int akh = (tid & 1) * 16;
    const __half* pA = A + (size_t)(m0 + arow) * 1024 + akh;
    const uint32_t adst = (uint32_t)(arow * ROWP + akh) * 2;
    const int brow = tid >> 2;
    const int bc = (tid & 3) * 8;
    const __half* pB = Bh + (size_t)(n0 + brow) * 1024 + bc;
    const uint32_t bdst = (uint32_t)(PLANEA + brow * ROWP + bc) * 2;

    auto issue = [&](int stage, int k0) {
        const uint32_t sb = sm_base + (uint32_t)stage * STG16 * 2;
        cp16(sb + adst,      pA + k0);
        cp16(sb + adst + 16, pA + k0 + 8);
        cp16(sb + bdst,      pB + k0);
        CP_COMMIT();
    };

    float acc[2][4][4];
    #pragma unroll
    for (int mt = 0; mt < 2; mt++)
        #pragma unroll
        for (int nt = 0; nt < 4; nt++)
            #pragma unroll
            for (int e = 0; e < 4; e++) acc[mt][nt][e] = 0.0f;

    const int lrow = lane & 15, lcol = (lane >> 4) * 8;

    issue(0, 0);
    issue(1, 32);

    for (int it = 0; it < 32; it++) {
        if (it < 31) asm volatile("cp.async.wait_group 1;");
        else         asm volatile("cp.async.wait_group 0;");
        __syncthreads();

        const int s = it - (it / 3) * 3;    // it % 3
        const uint32_t base_a = sm_base + (uint32_t)(s * STG16) * 2;
        const uint32_t base_b = base_a + (uint32_t)PLANEA * 2;

        #pragma unroll
        for (int ks = 0; ks < 2; ks++) {
            const uint32_t ko = (uint32_t)(ks * 16 + lcol) * 2;

            uint32_t bhi[4][2];
            #pragma unroll
            for (int j = 0; j < 2; j++) {
                const uint32_t off = (uint32_t)((wn*32 + j*16 + lrow) * ROWP) * 2 + ko;
                uint32_t r0, r1, r2, r3;
                LDSM4(r0, r1, r2, r3, base_b + off);
                bhi[2*j][0] = r0; bhi[2*j][1] = r2;
                bhi[2*j+1][0] = r1; bhi[2*j+1][1] = r3;
            }

            uint32_t af[2][4];
            #pragma unroll
            for (int mt = 0; mt < 2; mt++) {
                const uint32_t off = (uint32_t)((wm*32 + mt*16 + lrow) * ROWP) * 2 + ko;
                LDSM4(af[mt][0], af[mt][1], af[mt][2], af[mt][3], base_a + off);
            }
            #pragma unroll
            for (int mt = 0; mt < 2; mt++)
                #pragma unroll
                for (int nt = 0; nt < 4; nt++)
                    MMA_F16(acc[mt][nt], af[mt], bhi[nt]);
        }

        if (it + 2 < 32) {
            const int ns = (it + 2) - ((it + 2) / 3) * 3;
            issue(ns, (it + 2) * 32);
        }
    }

    const int gid = lane >> 2, tig = lane & 3;
    #pragma unroll
    for (int mt = 0; mt < 2; mt++)
        #pragma unroll
        for (int nt = 0; nt < 4; nt++) {
            const int mr = m0 + wm*32 + mt*16 + gid;
            const int nc = n0 + wn*32 + nt*8 + 2*tig;
            emit<MODE>(mr,     nc,     acc[mt][nt][0], bias, out);
            emit<MODE>(mr,     nc + 1, acc[mt][nt][1], bias, out);
            emit<MODE>(mr + 8, nc,     acc[mt][nt][2], bias, out);
            emit<MODE>(mr + 8, nc + 1, acc[mt][nt][3], bias, out);
        }
}

// ---------------------------------------------------------------------------
// Flash attention, split-KV (round-14 verified): grid (T/128, NBH, 2).
// ---------------------------------------------------------------------------
#define KVP 72
#define PLH (64*KVP)
#define PLHB (PLH*2)
#define STAGEB (4*PLHB)                         // K0,K1,V0,V1
static const int ATTN_SMEM = 2 * STAGEB;        // 73728 B

__global__ void __launch_bounds__(256) attn_mma() {
    extern __shared__ __align__(16) uint16_t asm16[];
    const int tid  = threadIdx.x;
    const int lane = tid & 31, w = tid >> 5;
    const int gid  = lane >> 2, qc = lane & 3;
    const int lrow = lane & 15, lhalf = (lane >> 4);
    const int qi = gridDim.x - 1 - blockIdx.x;   // heavy tiles first
    const int bh = blockIdx.y;
    const int sp = blockIdx.z;                   // kv split half

    const int nk  = qi + 1;                      // kv-64 tiles in this half
    const int kvb = sp * nk;                     // first kv-64 tile (global)
    const int nst = (nk + 1) >> 1;               // 128-kv stages

    const uint32_t smb = (uint32_t)__cvta_generic_to_shared(asm16);

    const __half* Khg = g_Kh  + (size_t)bh * T_ * HD_;
    const __half* Vhg = g_Vth + (size_t)bh * HD_ * T_;

    const int lr = tid >> 2, c4 = tid & 3;
    auto issue = [&](int st, int stIdx) {
        const uint32_t sb = smb + (uint32_t)st * STAGEB;
        const int kv0 = (kvb + stIdx * 2) * 64;
        #pragma unroll
        for (int h = 0; h < 2; h++) {
            const __half* kh = Khg + ((size_t)(kv0 + h*64) + lr) * 64;
            const __half* vh = Vhg + (size_t)lr * T_ + kv0 + h*64;
            const uint32_t kpl = sb + (uint32_t)h * PLHB;
            const uint32_t vpl = sb + (uint32_t)(2 + h) * PLHB;
            #pragma unroll
            for (int u = 0; u < 2; u++) {
                const int c = c4 + 4*u;
                const uint32_t d = (uint32_t)(lr*KVP + c*8) * 2;
                cp16(kpl + d, kh + c*8);
                cp16(vpl + d, vh + c*8);
            }
        }
        CP_COMMIT();
    };

    issue(0, 0);

    uint32_t qh[4][4];
    {
        const size_t qb = ((size_t)bh * T_ + qi*128 + w*16) * HD_;
        #pragma unroll
        for (int ks = 0; ks < 4; ks++)
            #pragma unroll
            for (int kh = 0; kh < 2; kh++)
                #pragma unroll
                for (int h2 = 0; h2 < 2; h2++) {
                    const size_t off = qb + (size_t)(gid + 8*h2)*HD_ + ks*16 + kh*8 + 2*qc;
                    qh[ks][h2 + 2*kh] = *(const uint32_t*)(g_Qh + off);
                }
    }

    float m0 = -1e30f, m1 = -1e30f, l0 = 0.0f, l1 = 0.0f;
    float oacc[8][4];
    #pragma unroll
    for (int dt = 0; dt < 8; dt++)
        #pragma unroll
        for (int e = 0; e < 4; e++) oacc[dt][e] = 0.0f;

    const int r0 = qi*128 + w*16 + gid;
    const int r1 = r0 + 8;
    const uint32_t lbase = (uint32_t)(lrow*KVP + lhalf*8) * 2;

    for (int st = 0; st < nst; st++) {
        if (st + 1 < nst) issue((st + 1) & 1, st + 1);
        if (st + 1 < nst) asm volatile("cp.async.wait_group 1;");
        else              asm volatile("cp.async.wait_group 0;");
        __syncthreads();

        const uint32_t sb = smb + (uint32_t)(st & 1) * STAGEB;

        #pragma unroll
        for (int h = 0; h < 2; h++) {
            const int ktl = 2*st + h;
            if (ktl >= nk) break;
            const int kt = kvb + ktl;
            const uint32_t kbh = sb + (uint32_t)h * PLHB;
            const uint32_t vbh = sb + (uint32_t)(2 + h) * PLHB;

            float sacc[8][4];
            #pragma unroll
            for (int nt = 0; nt < 8; nt++)
                #pragma unroll
                for (int e = 0; e < 4; e++) sacc[nt][e] = 0.0f;

            #pragma unroll
            for (int ks = 0; ks < 4; ks++) {
                #pragma unroll
                for (int np = 0; np < 4; np++) {
                    const uint32_t off = lbase + (uint32_t)(np*16*KVP + ks*16) * 2;
                    uint32_t h0, h1, h2, h3;
                    LDSM4(h0, h1, h2, h3, kbh + off);
                    uint32_t ba[2] = {h0, h2}, bb[2] = {h1, h3};
                    MMA_F16(sacc[2*np],   qh[ks], ba);
                    MMA_F16(sacc[2*np+1], qh[ks], bb);
                }
            }

            if (kt >= 2*qi) {
                #pragma unroll
                for (int nt = 0; nt < 8; nt++) {
                    const int c0 = kt*64 + nt*8 + 2*qc;
                    if (c0     > r0) sacc[nt][0] = -1e30f;
                    if (c0 + 1 > r0) sacc[nt][1] = -1e30f;
                    if (c0     > r1) sacc[nt][2] = -1e30f;
                    if (c0 + 1 > r1) sacc[nt][3] = -1e30f;
                }
            }

            float rm0 = -1e30f, rm1 = -1e30f;
            #pragma unroll
            for (int nt = 0; nt < 8; nt++) {
                rm0 = fmaxf(rm0, fmaxf(sacc[nt][0], sacc[nt][1]));
                rm1 = fmaxf(rm1, fmaxf(sacc[nt][2], sacc[nt][3]));
            }
            rm0 = fmaxf(rm0, __shfl_xor_sync(0xffffffffu, rm0, 1));
            rm0 = fmaxf(rm0, __shfl_xor_sync(0xffffffffu, rm0, 2));
            rm1 = fmaxf(rm1, __shfl_xor_sync(0xffffffffu, rm1, 1));
            rm1 = fmaxf(rm1, __shfl_xor_sync(0xffffffffu, rm1, 2));
            const float mn0 = fmaxf(m0, rm0), mn1 = fmaxf(m1, rm1);
            const float cr0 = ex2f(m0 - mn0), cr1 = ex2f(m1 - mn1);
            m0 = mn0; m1 = mn1;
            float s0 = 0.0f, s1 = 0.0f;
            #pragma unroll
            for (int nt = 0; nt < 8; nt++) {
                sacc[nt][0] = ex2f(sacc[nt][0] - mn0); s0 += sacc[nt][0];
                sacc[nt][1] = ex2f(sacc[nt][1] - mn0); s0 += sacc[nt][1];
                sacc[nt][2] = ex2f(sacc[nt][2] - mn1); s1 += sacc[nt][2];
                sacc[nt][3] = ex2f(sacc[nt][3] - mn1); s1 += sacc[nt][3];
            }
            s0 += __shfl_xor_sync(0xffffffffu, s0, 1);
            s0 += __shfl_xor_sync(0xffffffffu, s0, 2);
            s1 += __shfl_xor_sync(0xffffffffu, s1, 1);
            s1 += __shfl_xor_sync(0xffffffffu, s1, 2);
            l0 = l0 * cr0 + s0;
            l1 = l1 * cr1 + s1;
            #pragma unroll
            for (int dt = 0; dt < 8; dt++) {
                oacc[dt][0] *= cr0; oacc[dt][1] *= cr0;
                oacc[dt][2] *= cr1; oacc[dt][3] *= cr1;
            }

            #pragma unroll
            for (int kpv = 0; kpv < 4; kpv++) {
                uint32_t pa[4];
                pa[0] = pack2h(sacc[2*kpv][0],   sacc[2*kpv][1]);
                pa[1] = pack2h(sacc[2*kpv][2],   sacc[2*kpv][3]);
                pa[2] = pack2h(sacc[2*kpv+1][0], sacc[2*kpv+1][1]);
                pa[3] = pack2h(sacc[2*kpv+1][2], sacc[2*kpv+1][3]);
                #pragma unroll
                for (int np = 0; np < 4; np++) {
                    const uint32_t off = lbase + (uint32_t)(np*16*KVP + kpv*16) * 2;
                    uint32_t h0, h1, h2, h3;
                    LDSM4(h0, h1, h2, h3, vbh + off);
                    uint32_t va[2] = {h0, h2}, vb[2] = {h1, h3};
                    MMA_F16(oacc[2*np],   pa, va);
                    MMA_F16(oacc[2*np+1], pa, vb);
                }
            }
        }
        __syncthreads();
    }

    float*  Op = sp ? g_Op1 : g_Op0;
    float2* ml = sp ? g_ml1 : g_ml0;
    const size_t o0 = ((size_t)bh * T_ + r0) * HD_;
    const size_t o1 = ((size_t)bh * T_ + r1) * HD_;
    #pragma unroll
    for (int dt = 0; dt < 8; dt++) {
        const int d = dt*8 + 2*qc;
        *(float2*)(Op + o0 + d) = make_float2(oacc[dt][0], oacc[dt][1]);
        *(float2*)(Op + o1 + d) = make_float2(oacc[dt][2], oacc[dt][3]);
    }
    if (qc == 0) {
        ml[(size_t)bh * T_ + r0] = make_float2(m0, l0);
        ml[(size_t)bh * T_ + r1] = make_float2(m1, l1);
    }
}

// ---------------------------------------------------------------------------
// Combine (vectorized float4): 16 threads/row, 16 rows/block. (round-15 win)
// ---------------------------------------------------------------------------
__global__ void __launch_bounds__(256) attn_combine() {
    const int tid = threadIdx.x;
    const int row = blockIdx.x * 16 + (tid >> 4);   // bh*T + t
    const int d4  = (tid & 15) * 4;
    const float2 a = g_ml0[row];
    const float2 b2 = g_ml1[row];
    const float mm = fmaxf(a.x, b2.x);
    const float w0 = ex2f(a.x - mm), w1 = ex2f(b2.x - mm);
    const float inv = 1.0f / (a.y * w0 + b2.y * w1);
    const size_t o = (size_t)row * HD_ + d4;
    const float4 p0 = *(const float4*)(g_Op0 + o);
    const float4 p1 = *(const float4*)(g_Op1 + o);
    const float y0 = (p0.x * w0 + p1.x * w1) * inv;
    const float y1 = (p0.y * w0 + p1.y * w1) * inv;
    const float y2 = (p0.z * w0 + p1.z * w1) * inv;
    const float y3 = (p0.w * w0 + p1.w * w1) * inv;
    const int bh = row >> 11, t = row & 2047;
    const int b = bh >> 4, h = bh & 15;
    uint2 u = make_uint2(pack2h(y0, y1), pack2h(y2, y3));
    *(uint2*)(g_yh + ((size_t)(b * T_ + t)) * C_ + h * HD_ + d4) = u;
}

extern "C" void kernel_launch(void* const* d_in, const int* in_sizes, int n_in,
                              void* d_out, int out_size) {
    const float* x      = (const float*)d_in[0];
    const float* W_attn = (const float*)d_in[1];
    const float* b_attn = (const float*)d_in[2];
    const float* W_proj = (const float*)d_in[3];
    const float* b_proj = (const float*)d_in[4];
    float* out = (float*)d_out;

    cudaFuncSetAttribute(gemm_f16<0>, cudaFuncAttributeMaxDynamicSharedMemorySize, GEMM_SMEM);
    cudaFuncSetAttribute(gemm_f16<1>, cudaFuncAttributeMaxDynamicSharedMemorySize, GEMM_SMEM);
    cudaFuncSetAttribute(attn_mma,    cudaFuncAttributeMaxDynamicSharedMemorySize, ATTN_SMEM);

    __half *xh, *yh, *wah, *wph;
    cudaGetSymbolAddress((void**)&xh,  g_xh);  cudaGetSymbolAddress((void**)&yh,  g_yh);
    cudaGetSymbolAddress((void**)&wah, g_wah); cudaGetSymbolAddress((void**)&wph, g_wph);

    // converters
    round_f4<<<(M_*C_/4)/256, 256>>>(x, xh);
    round_wt<3*C_><<<dim3(3*C_/32, C_/32), 256>>>(W_attn, wah);
    round_wt<C_><<<dim3(C_/32, C_/32), 256>>>(W_proj, wph);

    // qkv (epilogue rounds Q (pre-scaled by log2e/8), K, transposed V)
    gemm_f16<0><<<dim3(3*C_/64, M_/128), 256, GEMM_SMEM>>>(xh, wah, b_attn, nullptr);
    // attention, split-KV halves + combine
    attn_mma<<<dim3(T_/128, NBH_, 2), 256, ATTN_SMEM>>>();
    attn_combine<<<(NBH_*T_)/16, 256>>>();
    // proj
    gemm_f16<1><<<dim3(C_/64, M_/128), 256, GEMM_SMEM>>>(yh, wph, b_proj, out);
}

// round 17
// speedup vs baseline: 1.5334x; 1.5334x over previous
#include <cuda_runtime.h>
#include <cuda_fp16.h>
#include <cstdint>
#include <math.h>

#define B_  2
#define T_  2048
#define C_  1024
#define H_  16
#define HD_ 64
#define NBH_ (B_*H_)     // 32
#define M_   (B_*T_)     // 4096

// Scratch (allocation-free: __device__ globals)
__device__ __half g_Qh[(size_t)NBH_ * T_ * HD_];   // pre-scaled by 0.125*log2(e)
__device__ __half g_Kh[(size_t)NBH_ * T_ * HD_];   // [bh][t][d]
__device__ __half g_Vth[(size_t)NBH_ * HD_ * T_];  // [bh][d][t]
__device__ __half g_xh[(size_t)M_ * C_];
__device__ __half g_yh[(size_t)M_ * C_];
__device__ __half g_wah[(size_t)3*C_ * C_];   // W_attn^T [n][k]
__device__ __half g_wph[(size_t)C_ * C_];     // W_proj^T [n][k]

// split-KV partials (unnormalized O + per-row (m,l))
__device__ float  g_Op0[(size_t)NBH_ * T_ * HD_];
__device__ float  g_Op1[(size_t)NBH_ * T_ * HD_];
__device__ float2 g_ml0[(size_t)NBH_ * T_];
__device__ float2 g_ml1[(size_t)NBH_ * T_];

#define QSCALE (0.125f * 1.4426950408889634f)   // (1/sqrt(64)) * log2(e)

// ---------------------------------------------------------------------------
// helpers
// ---------------------------------------------------------------------------
__device__ __forceinline__ uint32_t pack2h(float x, float y) {
    __half2 h = __floats2half2_rn(x, y);
    return *reinterpret_cast<uint32_t*>(&h);
}
__device__ __forceinline__ float ex2f(float x) {
    float r;
    asm("ex2.approx.f32 %0, %1;" : "=f"(r) : "f"(x));
    return r;
}

#define LDSM4(r0, r1, r2, r3, addr) \
    asm volatile("ldmatrix.sync.aligned.m8n8.x4.shared.b16 {%0,%1,%2,%3}, [%4];" \
        : "=r"(r0), "=r"(r1), "=r"(r2), "=r"(r3) : "r"(addr))

#define MMA_F16(d, a, b) \
    asm volatile("mma.sync.aligned.m16n8k16.row.col.f32.f16.f16.f32 " \
        "{%0,%1,%2,%3},{%4,%5,%6,%7},{%8,%9},{%0,%1,%2,%3};" \
        : "+f"((d)[0]), "+f"((d)[1]), "+f"((d)[2]), "+f"((d)[3]) \
        : "r"((a)[0]), "r"((a)[1]), "r"((a)[2]), "r"((a)[3]), \
          "r"((b)[0]), "r"((b)[1]))

__device__ __forceinline__ void cp16(uint32_t dst, const void* src) {
    asm volatile("cp.async.cg.shared.global [%0], [%1], 16;" :: "r"(dst), "l"(src));
}
#define CP_COMMIT() asm volatile("cp.async.commit_group;")

// ---------------------------------------------------------------------------
// Converters
// ---------------------------------------------------------------------------
__global__ void __launch_bounds__(256) round_f4(const float* __restrict__ src,
                                                __half* __restrict__ dst) {
    const int i = blockIdx.x * 256 + threadIdx.x;
    const float4 v = ((const float4*)src)[i];
    uint2 u = make_uint2(pack2h(v.x, v.y), pack2h(v.z, v.w));
    ((uint2*)dst)[i] = u;
}

template<int NC>
__global__ void __launch_bounds__(256) round_wt(const float* __restrict__ W,
                                                __half* __restrict__ th) {
    __shared__ float tile[32][33];
    const int n0 = blockIdx.x * 32, k0 = blockIdx.y * 32;
    const int tx = threadIdx.x & 31, ty = threadIdx.x >> 5;
    #pragma unroll
    for (int r = ty; r < 32; r += 8)
        tile[r][tx] = W[(size_t)(k0 + r) * NC + n0 + tx];
    __syncthreads();
    #pragma unroll
    for (int r = ty; r < 32; r += 8)
        th[(size_t)(n0 + r) * 1024 + k0 + tx] = __float2half_rn(tile[tx][r]);
}

// ---------------------------------------------------------------------------
// Epilogue scatter (bias added inside — verified fastest form)
// ---------------------------------------------------------------------------
template<int MODE>
__device__ __forceinline__ void emit(int m, int n, float val,
                                     const float* __restrict__ bias,
                                     float* __restrict__ out) {
    val += bias[n];
    if (MODE == 0) {
        const int bb = m >> 11;
        const int t  = m & 2047;
        if (n < C_) {
            const int h = n >> 6, d = n & 63;
            g_Qh[(((size_t)(bb*H_ + h))*T_ + t)*HD_ + d] = __float2half_rn(val * QSCALE);
        } else if (n < 2*C_) {
            const int nn = n - C_;
            const int h = nn >> 6, d = nn & 63;
            g_Kh[(((size_t)(bb*H_ + h))*T_ + t)*HD_ + d] = __float2half_rn(val);
        } else {
            const int nn = n - 2*C_;
            const int h = nn >> 6, d = nn & 63;
            g_Vth[(((size_t)(bb*H_ + h))*HD_ + d)*T_ + t] = __float2half_rn(val);  // transposed
        }
    } else {
        out[(size_t)m * C_ + n] = val;
    }
}

// ---------------------------------------------------------------------------
// fp16 GEMM (best-measured config: CTA 128x64, 256 thr, warp tile 32x32,
// K-chunk 32, 3-stage cp.async, pitch-80 smem)
// ---------------------------------------------------------------------------
#define ROWP 40
#define PLANEA (128*ROWP)
#define PLANEB (64*ROWP)
#define STG16  (PLANEA+PLANEB)
static const int GEMM_SMEM = 3 * STG16 * (int)sizeof(uint16_t);  // 46080 B

template<int MODE>
__global__ void __launch_bounds__(256, 4) gemm_f16(const __half* __restrict__ A,
                                                   const __half* __restrict__ Bh,
                                                   const float* __restrict__ bias,
                                                   float* __restrict__ out) {
    extern __shared__ __align__(16) uint16_t sm16[];
    const int tid  = threadIdx.x;
    const int lane = tid & 31, wid = tid >> 5;
    const int wm = wid >> 1, wn = wid & 1;          // 4m x 2n warps
    const int m0 = blockIdx.y * 128, n0 = blockIdx.x * 64;

    const uint32_t sm_base = (uint32_t)__cvta_generic_to_shared(sm16);

    const int arow = tid >> 1;
    const int akh = (tid & 1) * 16;
    const __half* pA = A + (size_t)(m0 + arow) * 1024 + akh;
    const uint32_t adst = (uint32_t)(arow * ROWP + akh) * 2;
    const int brow = tid >> 2;
    const int bc = (tid & 3) * 8;
    const __half* pB = Bh + (size_t)(n0 + brow) * 1024 + bc;
    const uint32_t bdst = (uint32_t)(PLANEA + brow * ROWP + bc) * 2;

    auto issue = [&](int stage, int k0) {
        const uint32_t sb = sm_base + (uint32_t)stage * STG16 * 2;
        cp16(sb + adst,      pA + k0);
        cp16(sb + adst + 16, pA + k0 + 8);
        cp16(sb + bdst,      pB + k0);
        CP_COMMIT();
    };

    float acc[2][4][4];
    #pragma unroll
    for (int mt = 0; mt < 2; mt++)
        #pragma unroll
        for (int nt = 0; nt < 4; nt++)
            #pragma unroll
            for (int e = 0; e < 4; e++) acc[mt][nt][e] = 0.0f;

    const int lrow = lane & 15, lcol = (lane >> 4) * 8;

    issue(0, 0);
    issue(1, 32);

    for (int it = 0; it < 32; it++) {
        if (it < 31) asm volatile("cp.async.wait_group 1;");
        else         asm volatile("cp.async.wait_group 0;");
        __syncthreads();

        const int s = it - (it / 3) * 3;    // it % 3
        const uint32_t base_a = sm_base + (uint32_t)(s * STG16) * 2;
        const uint32_t base_b = base_a + (uint32_t)PLANEA * 2;

        #pragma unroll
        for (int ks = 0; ks < 2; ks++) {
            const uint32_t ko = (uint32_t)(ks * 16 + lcol) * 2;

            uint32_t bhi[4][2];
            #pragma unroll
            for (int j = 0; j < 2; j++) {
                const uint32_t off = (uint32_t)((wn*32 + j*16 + lrow) * ROWP) * 2 + ko;
                uint32_t r0, r1, r2, r3;
                LDSM4(r0, r1, r2, r3, base_b + off);
                bhi[2*j][0] = r0; bhi[2*j][1] = r2;
                bhi[2*j+1][0] = r1; bhi[2*j+1][1] = r3;
            }

            uint32_t af[2][4];
            #pragma unroll
            for (int mt = 0; mt < 2; mt++) {
                const uint32_t off = (uint32_t)((wm*32 + mt*16 + lrow) * ROWP) * 2 + ko;
                LDSM4(af[mt][0], af[mt][1], af[mt][2], af[mt][3], base_a + off);
            }
            #pragma unroll
            for (int mt = 0; mt < 2; mt++)
                #pragma unroll
                for (int nt = 0; nt < 4; nt++)
                    MMA_F16(acc[mt][nt], af[mt], bhi[nt]);
        }

        if (it + 2 < 32) {
            const int ns = (it + 2) - ((it + 2) / 3) * 3;
            issue(ns, (it + 2) * 32);
        }
    }

    const int gid = lane >> 2, tig = lane & 3;
    #pragma unroll
    for (int mt = 0; mt < 2; mt++)
        #pragma unroll
        for (int nt = 0; nt < 4; nt++) {
            const int mr = m0 + wm*32 + mt*16 + gid;
            const int nc = n0 + wn*32 + nt*8 + 2*tig;
            emit<MODE>(mr,     nc,     acc[mt][nt][0], bias, out);
            emit<MODE>(mr,     nc + 1, acc[mt][nt][1], bias, out);
            emit<MODE>(mr + 8, nc,     acc[mt][nt][2], bias, out);
            emit<MODE>(mr + 8, nc + 1, acc[mt][nt][3], bias, out);
        }
}

// ---------------------------------------------------------------------------
// Flash attention, split-KV (verified): grid (T/128, NBH, 2).
// ---------------------------------------------------------------------------
#define KVP 72
#define PLH (64*KVP)
#define PLHB (PLH*2)
#define STAGEB (4*PLHB)                         // K0,K1,V0,V1
static const int ATTN_SMEM = 2 * STAGEB;        // 73728 B

__global__ void __launch_bounds__(256) attn_mma() {
    extern __shared__ __align__(16) uint16_t asm16[];
    const int tid  = threadIdx.x;
    const int lane = tid & 31, w = tid >> 5;
    const int gid  = lane >> 2, qc = lane & 3;
    const int lrow = lane & 15, lhalf = (lane >> 4);
    const int qi = gridDim.x - 1 - blockIdx.x;   // heavy tiles first
    const int bh = blockIdx.y;
    const int sp = blockIdx.z;                   // kv split half

    const int nk  = qi + 1;                      // kv-64 tiles in this half
    const int kvb = sp * nk;                     // first kv-64 tile (global)
    const int nst = (nk + 1) >> 1;               // 128-kv stages

    const uint32_t smb = (uint32_t)__cvta_generic_to_shared(asm16);

    const __half* Khg = g_Kh  + (size_t)bh * T_ * HD_;
    const __half* Vhg = g_Vth + (size_t)bh * HD_ * T_;

    const int lr = tid >> 2, c4 = tid & 3;
    auto issue = [&](int st, int stIdx) {
        const uint32_t sb = smb + (uint32_t)st * STAGEB;
        const int kv0 = (kvb + stIdx * 2) * 64;
        #pragma unroll
        for (int h = 0; h < 2; h++) {
            const __half* kh = Khg + ((size_t)(kv0 + h*64) + lr) * 64;
            const __half* vh = Vhg + (size_t)lr * T_ + kv0 + h*64;
            const uint32_t kpl = sb + (uint32_t)h * PLHB;
            const uint32_t vpl = sb + (uint32_t)(2 + h) * PLHB;
            #pragma unroll
            for (int u = 0; u < 2; u++) {
                const int c = c4 + 4*u;
                const uint32_t d = (uint32_t)(lr*KVP + c*8) * 2;
                cp16(kpl + d, kh + c*8);
                cp16(vpl + d, vh + c*8);
            }
        }
        CP_COMMIT();
    };

    issue(0, 0);

    uint32_t qh[4][4];
    {
        const size_t qb = ((size_t)bh * T_ + qi*128 + w*16) * HD_;
        #pragma unroll
        for (int ks = 0; ks < 4; ks++)
            #pragma unroll
            for (int kh = 0; kh < 2; kh++)
                #pragma unroll
                for (int h2 = 0; h2 < 2; h2++) {
                    const size_t off = qb + (size_t)(gid + 8*h2)*HD_ + ks*16 + kh*8 + 2*qc;
                    qh[ks][h2 + 2*kh] = *(const uint32_t*)(g_Qh + off);
                }
    }

    float m0 = -1e30f, m1 = -1e30f, l0 = 0.0f, l1 = 0.0f;
    float oacc[8][4];
    #pragma unroll
    for (int dt = 0; dt < 8; dt++)
        #pragma unroll
        for (int e = 0; e < 4; e++) oacc[dt][e] = 0.0f;

    const int r0 = qi*128 + w*16 + gid;
    const int r1 = r0 + 8;
    const uint32_t lbase = (uint32_t)(lrow*KVP + lhalf*8) * 2;

    for (int st = 0; st < nst; st++) {
        if (st + 1 < nst) issue((st + 1) & 1, st + 1);
        if (st + 1 < nst) asm volatile("cp.async.wait_group 1;");
        else              asm volatile("cp.async.wait_group 0;");
        __syncthreads();

        const uint32_t sb = smb + (uint32_t)(st & 1) * STAGEB;

        #pragma unroll
        for (int h = 0; h < 2; h++) {
            const int ktl = 2*st + h;
            if (ktl >= nk) break;
            const int kt = kvb + ktl;
            const uint32_t kbh = sb + (uint32_t)h * PLHB;
            const uint32_t vbh = sb + (uint32_t)(2 + h) * PLHB;

            float sacc[8][4];
            #pragma unroll
            for (int nt = 0; nt < 8; nt++)
                #pragma unroll
                for (int e = 0; e < 4; e++) sacc[nt][e] = 0.0f;

            #pragma unroll
            for (int ks = 0; ks < 4; ks++) {
                #pragma unroll
                for (int np = 0; np < 4; np++) {
                    const uint32_t off = lbase + (uint32_t)(np*16*KVP + ks*16) * 2;
                    uint32_t h0, h1, h2, h3;
                    LDSM4(h0, h1, h2, h3, kbh + off);
                    uint32_t ba[2] = {h0, h2}, bb[2] = {h1, h3};
                    MMA_F16(sacc[2*np],   qh[ks], ba);
                    MMA_F16(sacc[2*np+1], qh[ks], bb);
                }
            }

            if (kt >= 2*qi) {
                #pragma unroll
                for (int nt = 0; nt < 8; nt++) {
                    const int c0 = kt*64 + nt*8 + 2*qc;
                    if (c0     > r0) sacc[nt][0] = -1e30f;
                    if (c0 + 1 > r0) sacc[nt][1] = -1e30f;
                    if (c0     > r1) sacc[nt][2] = -1e30f;
                    if (c0 + 1 > r1) sacc[nt][3] = -1e30f;
                }
            }

            float rm0 = -1e30f, rm1 = -1e30f;
            #pragma unroll
            for (int nt = 0; nt < 8; nt++) {
                rm0 = fmaxf(rm0, fmaxf(sacc[nt][0], sacc[nt][1]));
                rm1 = fmaxf(rm1, fmaxf(sacc[nt][2], sacc[nt][3]));
            }
            rm0 = fmaxf(rm0, __shfl_xor_sync(0xffffffffu, rm0, 1));
            rm0 = fmaxf(rm0, __shfl_xor_sync(0xffffffffu, rm0, 2));
            rm1 = fmaxf(rm1, __shfl_xor_sync(0xffffffffu, rm1, 1));
            rm1 = fmaxf(rm1, __shfl_xor_sync(0xffffffffu, rm1, 2));
            const float mn0 = fmaxf(m0, rm0), mn1 = fmaxf(m1, rm1);
            const float cr0 = ex2f(m0 - mn0), cr1 = ex2f(m1 - mn1);
            m0 = mn0; m1 = mn1;
            float s0 = 0.0f, s1 = 0.0f;
            #pragma unroll
            for (int nt = 0; nt < 8; nt++) {
                sacc[nt][0] = ex2f(sacc[nt][0] - mn0); s0 += sacc[nt][0];
                sacc[nt][1] = ex2f(sacc[nt][1] - mn0); s0 += sacc[nt][1];
                sacc[nt][2] = ex2f(sacc[nt][2] - mn1); s1 += sacc[nt][2];
                sacc[nt][3] = ex2f(sacc[nt][3] - mn1); s1 += sacc[nt][3];
            }
            s0 += __shfl_xor_sync(0xffffffffu, s0, 1);
            s0 += __shfl_xor_sync(0xffffffffu, s0, 2);
            s1 += __shfl_xor_sync(0xffffffffu, s1, 1);
            s1 += __shfl_xor_sync(0xffffffffu, s1, 2);
            l0 = l0 * cr0 + s0;
            l1 = l1 * cr1 + s1;
            #pragma unroll
            for (int dt = 0; dt < 8; dt++) {
                oacc[dt][0] *= cr0; oacc[dt][1] *= cr0;
                oacc[dt][2] *= cr1; oacc[dt][3] *= cr1;
            }

            #pragma unroll
            for (int kpv = 0; kpv < 4; kpv++) {
                uint32_t pa[4];
                pa[0] = pack2h(sacc[2*kpv][0],   sacc[2*kpv][1]);
                pa[1] = pack2h(sacc[2*kpv][2],   sacc[2*kpv][3]);
                pa[2] = pack2h(sacc[2*kpv+1][0], sacc[2*kpv+1][1]);
                pa[3] = pack2h(sacc[2*kpv+1][2], sacc[2*kpv+1][3]);
                #pragma unroll
                for (int np = 0; np < 4; np++) {
                    const uint32_t off = lbase + (uint32_t)(np*16*KVP + kpv*16) * 2;
                    uint32_t h0, h1, h2, h3;
                    LDSM4(h0, h1, h2, h3, vbh + off);
                    uint32_t va[2] = {h0, h2}, vb[2] = {h1, h3};
                    MMA_F16(oacc[2*np],   pa, va);
                    MMA_F16(oacc[2*np+1], pa, vb);
                }
            }
        }
        __syncthreads();
    }

    float*  Op = sp ? g_Op1 : g_Op0;
    float2* ml = sp ? g_ml1 : g_ml0;
    const size_t o0 = ((size_t)bh * T_ + r0) * HD_;
    const size_t o1 = ((size_t)bh * T_ + r1) * HD_;
    #pragma unroll
    for (int dt = 0; dt < 8; dt++) {
        const int d = dt*8 + 2*qc;
        *(float2*)(Op + o0 + d) = make_float2(oacc[dt][0], oacc[dt][1]);
        *(float2*)(Op + o1 + d) = make_float2(oacc[dt][2], oacc[dt][3]);
    }
    if (qc == 0) {
        ml[(size_t)bh * T_ + r0] = make_float2(m0, l0);
        ml[(size_t)bh * T_ + r1] = make_float2(m1, l1);
    }
}

// ---------------------------------------------------------------------------
// Combine (vectorized float4): 16 threads/row, 16 rows/block.
// ---------------------------------------------------------------------------
__global__ void __launch_bounds__(256) attn_combine() {
    const int tid = threadIdx.x;
    const int row = blockIdx.x * 16 + (tid >> 4);   // bh*T + t
    const int d4  = (tid & 15) * 4;
    const float2 a = g_ml0[row];
    const float2 b2 = g_ml1[row];
    const float mm = fmaxf(a.x, b2.x);
    const float w0 = ex2f(a.x - mm), w1 = ex2f(b2.x - mm);
    const float inv = 1.0f / (a.y * w0 + b2.y * w1);
    const size_t o = (size_t)row * HD_ + d4;
    const float4 p0 = *(const float4*)(g_Op0 + o);
    const float4 p1 = *(const float4*)(g_Op1 + o);
    const float y0 = (p0.x * w0 + p1.x * w1) * inv;
    const float y1 = (p0.y * w0 + p1.y * w1) * inv;
    const float y2 = (p0.z * w0 + p1.z * w1) * inv;
    const float y3 = (p0.w * w0 + p1.w * w1) * inv;
    const int bh = row >> 11, t = row & 2047;
    const int b = bh >> 4, h = bh & 15;
    uint2 u = make_uint2(pack2h(y0, y1), pack2h(y2, y3));
    *(uint2*)(g_yh + ((size_t)(b * T_ + t)) * C_ + h * HD_ + d4) = u;
}

extern "C" void kernel_launch(void* const* d_in, const int* in_sizes, int n_in,
                              void* d_out, int out_size) {
    const float* x      = (const float*)d_in[0];
    const float* W_attn = (const float*)d_in[1];
    const float* b_attn = (const float*)d_in[2];
    const float* W_proj = (const float*)d_in[3];
    const float* b_proj = (const float*)d_in[4];
    float* out = (float*)d_out;

    cudaFuncSetAttribute(gemm_f16<0>, cudaFuncAttributeMaxDynamicSharedMemorySize, GEMM_SMEM);
    cudaFuncSetAttribute(gemm_f16<1>, cudaFuncAttributeMaxDynamicSharedMemorySize, GEMM_SMEM);
    cudaFuncSetAttribute(attn_mma,    cudaFuncAttributeMaxDynamicSharedMemorySize, ATTN_SMEM);

    __half *xh, *yh, *wah, *wph;
    cudaGetSymbolAddress((void**)&xh,  g_xh);  cudaGetSymbolAddress((void**)&yh,  g_yh);
    cudaGetSymbolAddress((void**)&wah, g_wah); cudaGetSymbolAddress((void**)&wph, g_wph);

    // converters
    round_f4<<<(M_*C_/4)/256, 256>>>(x, xh);
    round_wt<3*C_><<<dim3(3*C_/32, C_/32), 256>>>(W_attn, wah);
    round_wt<C_><<<dim3(C_/32, C_/32), 256>>>(W_proj, wph);

    // qkv (epilogue rounds Q (pre-scaled by log2e/8), K, transposed V)
    gemm_f16<0><<<dim3(3*C_/64, M_/128), 256, GEMM_SMEM>>>(xh, wah, b_attn, nullptr);
    // attention, split-KV halves + combine
    attn_mma<<<dim3(T_/128, NBH_, 2), 256, ATTN_SMEM>>>();
    attn_combine<<<(NBH_*T_)/16, 256>>>();
    // proj
    gemm_f16<1><<<dim3(C_/64, M_/128), 256, GEMM_SMEM>>>(yh, wph, b_proj, out);
}